// round 14
// baseline (speedup 1.0000x reference)
#include <cuda_runtime.h>
#include <cuda_bf16.h>
#include <cstdint>

// Problem constants (fixed shapes from the reference)
#define H     40
#define KPTS  15
#define CIN   128
#define COUT  128
#define NMAX  20000
#define KDIM  (KPTS * CIN)   // 1920
#define KP_EXTENT_INV (1.0f / 1.2f)

// ---------------------------------------------------------------------------
// Static scratch: split-bf16 operands + split-K partial outputs.
// ---------------------------------------------------------------------------
__device__ __nv_bfloat16 g_Ahi[(size_t)NMAX * KDIM];
__device__ __nv_bfloat16 g_Alo[(size_t)NMAX * KDIM];
__device__ __nv_bfloat16 g_Bhi[(size_t)COUT * KDIM];
__device__ __nv_bfloat16 g_Blo[(size_t)COUT * KDIM];
#define SPLITK 3
__device__ float         g_Cpart[SPLITK][(size_t)NMAX * COUT];   // split-K partials

// ---------------------------------------------------------------------------
// PTX helpers (baseline sm_75/80+ instructions — safe for compute_103)
// ---------------------------------------------------------------------------
__device__ __forceinline__ uint32_t smem_u32(const void* p) {
    uint32_t a;
    asm("{ .reg .u64 t; cvta.to.shared.u64 t, %1; cvt.u32.u64 %0, t; }" : "=r"(a) : "l"(p));
    return a;
}
__device__ __forceinline__ void cp_async16(uint32_t dst, const void* src) {
    asm volatile("cp.async.cg.shared.global [%0], [%1], 16;\n" :: "r"(dst), "l"(src) : "memory");
}
__device__ __forceinline__ void cp_async_commit() {
    asm volatile("cp.async.commit_group;" ::: "memory");
}
template <int NN>
__device__ __forceinline__ void cp_async_wait() {
    asm volatile("cp.async.wait_group %0;" :: "n"(NN) : "memory");
}
__device__ __forceinline__ void ldm_x4(uint32_t& r0, uint32_t& r1, uint32_t& r2, uint32_t& r3,
                                       uint32_t addr) {
    asm volatile("ldmatrix.sync.aligned.m8n8.x4.shared.b16 {%0,%1,%2,%3}, [%4];"
                 : "=r"(r0), "=r"(r1), "=r"(r2), "=r"(r3) : "r"(addr));
}
__device__ __forceinline__ void ldm_x4_trans(uint32_t& r0, uint32_t& r1, uint32_t& r2, uint32_t& r3,
                                             uint32_t addr) {
    asm volatile("ldmatrix.sync.aligned.m8n8.x4.trans.shared.b16 {%0,%1,%2,%3}, [%4];"
                 : "=r"(r0), "=r"(r1), "=r"(r2), "=r"(r3) : "r"(addr));
}
__device__ __forceinline__ void mma_bf16(float& c0, float& c1, float& c2, float& c3,
                                         uint32_t a0, uint32_t a1, uint32_t a2, uint32_t a3,
                                         uint32_t b0, uint32_t b1) {
    asm volatile("mma.sync.aligned.m16n8k16.row.col.f32.bf16.bf16.f32 "
                 "{%0,%1,%2,%3}, {%4,%5,%6,%7}, {%8,%9}, {%0,%1,%2,%3};"
                 : "+f"(c0), "+f"(c1), "+f"(c2), "+f"(c3)
                 : "r"(a0), "r"(a1), "r"(a2), "r"(a3), "r"(b0), "r"(b1));
}

__device__ __forceinline__ void split_bf16(float v, __nv_bfloat16& hi, __nv_bfloat16& lo) {
    hi = __float2bfloat16_rn(v);
    lo = __float2bfloat16_rn(v - __bfloat162float(hi));
}
__device__ __forceinline__ unsigned short bits(__nv_bfloat16 v) {
    return __bfloat16_as_ushort(v);
}

// SW128 swizzled byte offset for (row r [128B rows], 16B segment seg)
__device__ __forceinline__ uint32_t swz(int r, int seg) {
    return (uint32_t)(r * 128 + ((seg * 16) ^ ((r & 7) * 16)));
}

// ---------------------------------------------------------------------------
// Kernel 1 (combined): blocks [0, BPREP_BLOCKS) transpose+split the weights;
// remaining blocks: per-query TENSOR-CORE step A.
//   weighted[n] = W_infl[16(k) x 48(h)] @ X_nb[48(h) x 128(c)]
// via mma.sync bf16 split (Whi·Xhi + Whi·Xlo + Wlo·Xhi), fp32 accum.
// 256 threads, NQ queries per CTA processed serially.
// ---------------------------------------------------------------------------
#define BPREP_BLOCKS ((KDIM / 32) * (COUT / 32))   // 60 * 4 = 240
#define NQ 8

__global__ void __launch_bounds__(256, 3) kp_prep_weight_kernel(
    const float* __restrict__ W,        // [KDIM, COUT]
    const float* __restrict__ q_pts,    // [N,3]
    const float* __restrict__ s_pts,    // [Ns,3]
    const int*   __restrict__ nb,       // [N,H]
    const float* __restrict__ x,        // [Ns,CIN]
    const float* __restrict__ kp,       // [KPTS,3]
    int N, int Ns)
{
    __shared__ float tile[32][33];
    __shared__ float s_kp[48];
    __shared__ int   s_qidx[H];
    // X: [48 h-rows][128 ch] bf16, 256B rows, row-XOR swizzle (16B grain)
    __shared__ __align__(256) unsigned char sXhi[48 * 256];
    __shared__ __align__(256) unsigned char sXlo[48 * 256];
    // W: [16 k-rows][64 h-cols] bf16, 128B rows, swz()
    __shared__ __align__(128) unsigned char sWhi[16 * 128];
    __shared__ __align__(128) unsigned char sWlo[16 * 128];

    if (blockIdx.x < BPREP_BLOCKS) {
        // ---- B prep: smem-tiled transpose + hi/lo split (proven) ----
        int b  = blockIdx.x;
        int k0 = (b % (KDIM / 32)) * 32;
        int n0 = (b / (KDIM / 32)) * 32;
        int tx = threadIdx.x & 31;
        int ty = threadIdx.x >> 5;      // 0..7

        #pragma unroll
        for (int j = 0; j < 4; ++j)
            tile[ty + 8 * j][tx] = W[(size_t)(k0 + ty + 8 * j) * COUT + n0 + tx];
        __syncthreads();

        #pragma unroll
        for (int j = 0; j < 4; ++j) {
            int n = n0 + ty + 8 * j;
            float v = tile[tx][ty + 8 * j];
            __nv_bfloat16 hi, lo;
            split_bf16(v, hi, lo);
            g_Bhi[(size_t)n * KDIM + k0 + tx] = hi;
            g_Blo[(size_t)n * KDIM + k0 + tx] = lo;
        }
        return;
    }

    int t    = threadIdx.x;
    int wid  = t >> 5;
    int lane = t & 31;

    if (t < KPTS * 3) s_kp[t] = kp[t];
    // Zero pads ONCE: X rows 40..47 (never written per-query), full W tiles
    // (per-query writes are a bijective swizzle image of valid h<40 region;
    //  pad region bytes stay zero forever).
    for (int i = t; i < (8 * 256) / 4; i += 256) {
        ((uint32_t*)(sXhi + 40 * 256))[i] = 0;
        ((uint32_t*)(sXlo + 40 * 256))[i] = 0;
    }
    for (int i = t; i < (16 * 128) / 4; i += 256) {
        ((uint32_t*)sWhi)[i] = 0;
        ((uint32_t*)sWlo)[i] = 0;
    }

    uint32_t uXhi = smem_u32(sXhi), uXlo = smem_u32(sXlo);
    uint32_t uWhi = smem_u32(sWhi), uWlo = smem_u32(sWlo);

    int qbase = (blockIdx.x - BPREP_BLOCKS) * NQ;

    for (int q = 0; q < NQ; ++q) {
        int n = qbase + q;
        bool act = (n < N);

        // Protect previous query's ldmatrix reads before overwriting smem.
        __syncthreads();

        // ---- Phase 0: indices + influence weights (threads 0..39) ----
        if (act && t < H) {
            int h = t;
            float qx = q_pts[n * 3 + 0];
            float qy = q_pts[n * 3 + 1];
            float qz = q_pts[n * 3 + 2];
            int idx = nb[(size_t)n * H + h];
            bool valid = ((unsigned)idx < (unsigned)Ns);
            int safe = valid ? idx : 0;
            s_qidx[h] = safe;
            float px = s_pts[(size_t)safe * 3 + 0] - qx;
            float py = s_pts[(size_t)safe * 3 + 1] - qy;
            float pz = s_pts[(size_t)safe * 3 + 2] - qz;
            #pragma unroll
            for (int k = 0; k < KPTS; k++) {
                float dx = px - s_kp[k * 3 + 0];
                float dy = py - s_kp[k * 3 + 1];
                float dz = pz - s_kp[k * 3 + 2];
                float d2 = dx * dx + dy * dy + dz * dz;
                float w  = fmaxf(1.0f - sqrtf(d2) * KP_EXTENT_INV, 0.0f);
                w = valid ? w : 0.0f;
                __nv_bfloat16 wh, wl;
                split_bf16(w, wh, wl);
                uint32_t off = (uint32_t)(k * 128 + ((2 * h) ^ ((k & 7) * 16)));
                *(__nv_bfloat16*)(sWhi + off) = wh;
                *(__nv_bfloat16*)(sWlo + off) = wl;
            }
        }
        __syncthreads();

        // ---- Phase 1: gather + convert X rows (warp per h-row, 5 rows each) ----
        if (act) {
            #pragma unroll
            for (int i = 0; i < 5; ++i) {
                int h = wid + 8 * i;           // covers 0..39 exactly
                int idx = s_qidx[h];
                float4 v = *(const float4*)(x + (size_t)idx * CIN + lane * 4);
                __nv_bfloat16 h0, h1, h2, h3, l0, l1, l2, l3;
                split_bf16(v.x, h0, l0);
                split_bf16(v.y, h1, l1);
                split_bf16(v.z, h2, l2);
                split_bf16(v.w, h3, l3);
                uint32_t off = (uint32_t)(h * 256 + ((lane * 8) ^ ((h & 7) * 16)));
                *(ushort4*)(sXhi + off) = make_ushort4(bits(h0), bits(h1), bits(h2), bits(h3));
                *(ushort4*)(sXlo + off) = make_ushort4(bits(l0), bits(l1), bits(l2), bits(l3));
            }
        }
        __syncthreads();

        // ---- Phase 2: mma + store. Warp owns 16 channels (2 n-tiles). ----
        if (act) {
            int c0w = wid * 16;
            float d0[4] = {0.f, 0.f, 0.f, 0.f};
            float d1[4] = {0.f, 0.f, 0.f, 0.f};

            #pragma unroll
            for (int ks = 0; ks < 3; ++ks) {
                // A fragments (W tiles) — exact kernel2 A-path layout
                int ar = lane & 15;
                uint32_t aoff = (uint32_t)(ar * 128 +
                                (((ks * 2 + (lane >> 4)) * 16) ^ ((ar & 7) * 16)));
                uint32_t ah0, ah1, ah2, ah3, al0, al1, al2, al3;
                ldm_x4(ah0, ah1, ah2, ah3, uWhi + aoff);
                ldm_x4(al0, al1, al2, al3, uWlo + aoff);

                // B fragments via ldmatrix.trans on [h][c] storage:
                // tiles: (k_lo,c0) (k_hi,c0) (k_lo,c0+8) (k_hi,c0+8)
                int brow = ks * 16 + (lane & 7) + ((lane >> 3) & 1) * 8;
                uint32_t bcol = (uint32_t)(c0w * 2 + ((lane >> 4) * 16));
                uint32_t boff = (uint32_t)(brow * 256 + (bcol ^ ((brow & 7) * 16)));
                uint32_t bh0, bh1, bh2, bh3, bl0, bl1, bl2, bl3;
                ldm_x4_trans(bh0, bh1, bh2, bh3, uXhi + boff);
                ldm_x4_trans(bl0, bl1, bl2, bl3, uXlo + boff);

                // 3-product accumulation, 2 n-tiles
                mma_bf16(d0[0], d0[1], d0[2], d0[3], ah0, ah1, ah2, ah3, bh0, bh1);
                mma_bf16(d0[0], d0[1], d0[2], d0[3], ah0, ah1, ah2, ah3, bl0, bl1);
                mma_bf16(d0[0], d0[1], d0[2], d0[3], al0, al1, al2, al3, bh0, bh1);
                mma_bf16(d1[0], d1[1], d1[2], d1[3], ah0, ah1, ah2, ah3, bh2, bh3);
                mma_bf16(d1[0], d1[1], d1[2], d1[3], ah0, ah1, ah2, ah3, bl2, bl3);
                mma_bf16(d1[0], d1[1], d1[2], d1[3], al0, al1, al2, al3, bh2, bh3);
            }

            // Store D -> g_Ahi/g_Alo (rows k = lane>>2 and +8; skip k==15)
            int k1 = lane >> 2;
            int k2 = k1 + 8;
            size_t base = (size_t)n * KDIM;
            #pragma unroll
            for (int nt = 0; nt < 2; ++nt) {
                float* dd = nt ? d1 : d0;
                int c = c0w + nt * 8 + 2 * (lane & 3);
                {
                    __nv_bfloat16 a0, b0, a1, b1;
                    split_bf16(dd[0], a0, b0);
                    split_bf16(dd[1], a1, b1);
                    *(ushort2*)(g_Ahi + base + (size_t)k1 * CIN + c) = make_ushort2(bits(a0), bits(a1));
                    *(ushort2*)(g_Alo + base + (size_t)k1 * CIN + c) = make_ushort2(bits(b0), bits(b1));
                }
                if (k2 < KPTS) {
                    __nv_bfloat16 a0, b0, a1, b1;
                    split_bf16(dd[2], a0, b0);
                    split_bf16(dd[3], a1, b1);
                    *(ushort2*)(g_Ahi + base + (size_t)k2 * CIN + c) = make_ushort2(bits(a0), bits(a1));
                    *(ushort2*)(g_Alo + base + (size_t)k2 * CIN + c) = make_ushort2(bits(b0), bits(b1));
                }
            }
        }
    }
}

// ---------------------------------------------------------------------------
// Kernel 2: mma.sync bf16 split GEMM, SPLIT-K = 3 (unchanged — proven).
// ---------------------------------------------------------------------------
#define KC        64
#define CHUNKS    (KDIM / KC)        // 30
#define CHUNKS_PK (CHUNKS / SPLITK)  // 10
#define SA_H  0
#define SA_L  8192
#define SB_H  16384
#define SB_L  32768
#define ST_BYTES 49152
#define SMEM_TOTAL (2 * ST_BYTES)    // 96 KB

__global__ void __launch_bounds__(256, 2) kp_mma_gemm_kernel(int N)
{
    extern __shared__ char smem[];
    uint32_t sbase = smem_u32(smem);
    int tid  = threadIdx.x;
    int wid  = tid >> 5;
    int lane = tid & 31;

    int mt    = blockIdx.x / SPLITK;
    int kz    = blockIdx.x % SPLITK;
    int m0    = mt * 64;
    int cbase = kz * CHUNKS_PK;

    float* Cp_out = g_Cpart[kz];

    int wm = wid & 1;
    int wn = wid >> 1;

    int seg = tid & 7;
    int rb  = tid >> 3;

    const __nv_bfloat16* Ah = g_Ahi;
    const __nv_bfloat16* Al = g_Alo;
    const __nv_bfloat16* Bh = g_Bhi;
    const __nv_bfloat16* Bl = g_Blo;

    float acc[2][4][4];
    #pragma unroll
    for (int i = 0; i < 2; i++)
        #pragma unroll
        for (int j = 0; j < 4; j++)
            #pragma unroll
            for (int q = 0; q < 4; q++) acc[i][j][q] = 0.0f;

    auto load_chunk = [&](int stage, int c) {
        uint32_t sb = sbase + stage * ST_BYTES;
        size_t c0 = (size_t)c * KC + (size_t)seg * 8;
        #pragma unroll
        for (int g = 0; g < 2; ++g) {
            int r  = g * 32 + rb;
            int ra = m0 + r; if (ra >= N) ra = N - 1;
            uint32_t off = swz(r, seg);
            cp_async16(sb + SA_H + off, Ah + (size_t)ra * KDIM + c0);
            cp_async16(sb + SA_L + off, Al + (size_t)ra * KDIM + c0);
        }
        #pragma unroll
        for (int g = 0; g < 4; ++g) {
            int r = g * 32 + rb;
            uint32_t off = swz(r, seg);
            cp_async16(sb + SB_H + off, Bh + (size_t)r * KDIM + c0);
            cp_async16(sb + SB_L + off, Bl + (size_t)r * KDIM + c0);
        }
        cp_async_commit();
    };

    int a_r15 = lane & 15;
    int a_kx  = lane >> 4;
    int b_r   = ((lane >> 4) << 3) + (lane & 7);
    int b_kx  = (lane >> 3) & 1;

    load_chunk(0, cbase);

    for (int ci = 0; ci < CHUNKS_PK; ++ci) {
        int cur = ci & 1;
        if (ci + 1 < CHUNKS_PK) load_chunk(cur ^ 1, cbase + ci + 1);

        if (ci + 1 < CHUNKS_PK) cp_async_wait<1>();
        else                    cp_async_wait<0>();
        __syncthreads();

        uint32_t sb = sbase + cur * ST_BYTES;

        #pragma unroll
        for (int ks = 0; ks < 4; ++ks) {
            uint32_t ah[2][4], al[2][4];
            #pragma unroll
            for (int mtt = 0; mtt < 2; ++mtt) {
                int r  = wm * 32 + mtt * 16 + a_r15;
                int sg = ks * 2 + a_kx;
                uint32_t off = swz(r, sg);
                ldm_x4(ah[mtt][0], ah[mtt][1], ah[mtt][2], ah[mtt][3], sb + SA_H + off);
                ldm_x4(al[mtt][0], al[mtt][1], al[mtt][2], al[mtt][3], sb + SA_L + off);
            }
            uint32_t bh[4][2], bl[4][2];
            #pragma unroll
            for (int nt2 = 0; nt2 < 2; ++nt2) {
                int r  = wn * 32 + nt2 * 16 + b_r;
                int sg = ks * 2 + b_kx;
                uint32_t off = swz(r, sg);
                uint32_t r0, r1, r2, r3;
                ldm_x4(r0, r1, r2, r3, sb + SB_H + off);
                bh[nt2 * 2 + 0][0] = r0; bh[nt2 * 2 + 0][1] = r1;
                bh[nt2 * 2 + 1][0] = r2; bh[nt2 * 2 + 1][1] = r3;
                ldm_x4(r0, r1, r2, r3, sb + SB_L + off);
                bl[nt2 * 2 + 0][0] = r0; bl[nt2 * 2 + 0][1] = r1;
                bl[nt2 * 2 + 1][0] = r2; bl[nt2 * 2 + 1][1] = r3;
            }
            #pragma unroll
            for (int mtt = 0; mtt < 2; ++mtt)
                #pragma unroll
                for (int nt = 0; nt < 4; ++nt) {
                    float* cc = acc[mtt][nt];
                    mma_bf16(cc[0], cc[1], cc[2], cc[3],
                             ah[mtt][0], ah[mtt][1], ah[mtt][2], ah[mtt][3],
                             bh[nt][0], bh[nt][1]);
                    mma_bf16(cc[0], cc[1], cc[2], cc[3],
                             ah[mtt][0], ah[mtt][1], ah[mtt][2], ah[mtt][3],
                             bl[nt][0], bl[nt][1]);
                    mma_bf16(cc[0], cc[1], cc[2], cc[3],
                             al[mtt][0], al[mtt][1], al[mtt][2], al[mtt][3],
                             bh[nt][0], bh[nt][1]);
                }
        }
        __syncthreads();
    }

    int tq = lane >> 2;
    int tr = (lane & 3) * 2;
    #pragma unroll
    for (int mtt = 0; mtt < 2; ++mtt) {
        #pragma unroll
        for (int nt = 0; nt < 4; ++nt) {
            int gm = m0 + wm * 32 + mtt * 16 + tq;
            int gn = wn * 32 + nt * 8 + tr;
            float* cc = acc[mtt][nt];
            if (gm < N)     *(float2*)&Cp_out[(size_t)gm * COUT + gn]       = make_float2(cc[0], cc[1]);
            if (gm + 8 < N) *(float2*)&Cp_out[(size_t)(gm + 8) * COUT + gn] = make_float2(cc[2], cc[3]);
        }
    }
}

// ---------------------------------------------------------------------------
// Kernel 3: combine split-K partials.  out = p0 + p1 + p2  (float4 vectorized)
// ---------------------------------------------------------------------------
__global__ void __launch_bounds__(256) kp_splitk_add_kernel(float* __restrict__ out, int total4)
{
    int i = blockIdx.x * blockDim.x + threadIdx.x;
    if (i < total4) {
        const float4* p0 = (const float4*)g_Cpart[0];
        const float4* p1 = (const float4*)g_Cpart[1];
        const float4* p2 = (const float4*)g_Cpart[2];
        float4 a = p0[i];
        float4 b = p1[i];
        float4 c = p2[i];
        ((float4*)out)[i] = make_float4(a.x + b.x + c.x, a.y + b.y + c.y,
                                        a.z + b.z + c.z, a.w + b.w + c.w);
    }
}

// ---------------------------------------------------------------------------
// kernel_launch
// Inputs: q_pts [N,3] f32, s_pts [Ns,3] f32, neighb_inds [N,H] i32,
// x [Ns,CIN] f32, kernel_points [KPTS,3] f32, weights [KPTS,CIN,COUT] f32.
// Output: [N,COUT] f32.
// ---------------------------------------------------------------------------
extern "C" void kernel_launch(void* const* d_in, const int* in_sizes, int n_in,
                              void* d_out, int out_size)
{
    const float* q_pts = (const float*)d_in[0];
    const float* s_pts = (const float*)d_in[1];
    const int*   nb    = (const int*)d_in[2];
    const float* x     = (const float*)d_in[3];
    const float* kp    = (const float*)d_in[4];
    const float* w     = (const float*)d_in[5];
    float*       out   = (float*)d_out;

    int N  = in_sizes[0] / 3;
    int Ns = in_sizes[1] / 3;

    static int smem_set = 0;
    if (!smem_set) {
        cudaFuncSetAttribute(kp_mma_gemm_kernel,
                             cudaFuncAttributeMaxDynamicSharedMemorySize, SMEM_TOTAL);
        smem_set = 1;
    }

    int grid1 = BPREP_BLOCKS + (N + NQ - 1) / NQ;
    kp_prep_weight_kernel<<<grid1, 256>>>(w, q_pts, s_pts, nb, x, kp, N, Ns);

    int mtiles = (N + 63) / 64;
    kp_mma_gemm_kernel<<<mtiles * SPLITK, 256, SMEM_TOTAL>>>(N);

    int total4 = (N * COUT) / 4;
    kp_splitk_add_kernel<<<(total4 + 255) / 256, 256>>>(out, total4);
}

// round 16
// speedup vs baseline: 1.1156x; 1.1156x over previous
#include <cuda_runtime.h>
#include <cuda_bf16.h>
#include <cstdint>

// Problem constants (fixed shapes from the reference)
#define H     40
#define KPTS  15
#define CIN   128
#define COUT  128
#define NMAX  20000
#define KDIM  (KPTS * CIN)   // 1920
#define KP_EXTENT_INV (1.0f / 1.2f)

// ---------------------------------------------------------------------------
// Static scratch: split-bf16 operands + split-K partial outputs.
// ---------------------------------------------------------------------------
__device__ __nv_bfloat16 g_Ahi[(size_t)NMAX * KDIM];
__device__ __nv_bfloat16 g_Alo[(size_t)NMAX * KDIM];
__device__ __nv_bfloat16 g_Bhi[(size_t)COUT * KDIM];
__device__ __nv_bfloat16 g_Blo[(size_t)COUT * KDIM];
#define SPLITK 3
__device__ float         g_Cpart[SPLITK][(size_t)NMAX * COUT];   // split-K partials

// ---------------------------------------------------------------------------
// PTX helpers (baseline sm_75/80+ instructions — safe for compute_103)
// ---------------------------------------------------------------------------
__device__ __forceinline__ uint32_t smem_u32(const void* p) {
    uint32_t a;
    asm("{ .reg .u64 t; cvta.to.shared.u64 t, %1; cvt.u32.u64 %0, t; }" : "=r"(a) : "l"(p));
    return a;
}
__device__ __forceinline__ void cp_async16(uint32_t dst, const void* src) {
    asm volatile("cp.async.cg.shared.global [%0], [%1], 16;\n" :: "r"(dst), "l"(src) : "memory");
}
__device__ __forceinline__ void cp_async_commit() {
    asm volatile("cp.async.commit_group;" ::: "memory");
}
template <int NN>
__device__ __forceinline__ void cp_async_wait() {
    asm volatile("cp.async.wait_group %0;" :: "n"(NN) : "memory");
}
__device__ __forceinline__ void ldm_x4(uint32_t& r0, uint32_t& r1, uint32_t& r2, uint32_t& r3,
                                       uint32_t addr) {
    asm volatile("ldmatrix.sync.aligned.m8n8.x4.shared.b16 {%0,%1,%2,%3}, [%4];"
                 : "=r"(r0), "=r"(r1), "=r"(r2), "=r"(r3) : "r"(addr));
}
__device__ __forceinline__ void ldm_x4_trans(uint32_t& r0, uint32_t& r1, uint32_t& r2, uint32_t& r3,
                                             uint32_t addr) {
    asm volatile("ldmatrix.sync.aligned.m8n8.x4.trans.shared.b16 {%0,%1,%2,%3}, [%4];"
                 : "=r"(r0), "=r"(r1), "=r"(r2), "=r"(r3) : "r"(addr));
}
__device__ __forceinline__ void mma_bf16(float& c0, float& c1, float& c2, float& c3,
                                         uint32_t a0, uint32_t a1, uint32_t a2, uint32_t a3,
                                         uint32_t b0, uint32_t b1) {
    asm volatile("mma.sync.aligned.m16n8k16.row.col.f32.bf16.bf16.f32 "
                 "{%0,%1,%2,%3}, {%4,%5,%6,%7}, {%8,%9}, {%0,%1,%2,%3};"
                 : "+f"(c0), "+f"(c1), "+f"(c2), "+f"(c3)
                 : "r"(a0), "r"(a1), "r"(a2), "r"(a3), "r"(b0), "r"(b1));
}

__device__ __forceinline__ void split_bf16(float v, __nv_bfloat16& hi, __nv_bfloat16& lo) {
    hi = __float2bfloat16_rn(v);
    lo = __float2bfloat16_rn(v - __bfloat162float(hi));
}
__device__ __forceinline__ unsigned short bits(__nv_bfloat16 v) {
    return __bfloat16_as_ushort(v);
}

// SW128 swizzled byte offset for (row r [128B rows], 16B segment seg)
__device__ __forceinline__ uint32_t swz(int r, int seg) {
    return (uint32_t)(r * 128 + ((seg * 16) ^ ((r & 7) * 16)));
}

// ---------------------------------------------------------------------------
// Kernel 1 (combined): blocks [0, BPREP_BLOCKS) transpose+split the weights;
// remaining blocks: per-query TENSOR-CORE step A, SOFTWARE-PIPELINED.
//   weighted[n] = W_infl[16(k) x 48(h)] @ X_nb[48(h) x 128(c)]
// Double-buffered X/W smem stages; ONE __syncthreads per query:
//   iter q: sync; produce(q+1 -> buf^1); consume(q from buf).
// mma fragment paths identical to R14 (numerically proven).
// ---------------------------------------------------------------------------
#define BPREP_BLOCKS ((KDIM / 32) * (COUT / 32))   // 60 * 4 = 240
#define NQ 8

// dynamic smem stage layout (bytes)
#define PX_H   0
#define PX_L   12288
#define PW_H   24576
#define PW_L   26624
#define STAGE_B 28672
#define PREP_DYN (2 * STAGE_B)    // 57344

__global__ void __launch_bounds__(256, 3) kp_prep_weight_kernel(
    const float* __restrict__ W,        // [KDIM, COUT]
    const float* __restrict__ q_pts,    // [N,3]
    const float* __restrict__ s_pts,    // [Ns,3]
    const int*   __restrict__ nb,       // [N,H]
    const float* __restrict__ x,        // [Ns,CIN]
    const float* __restrict__ kp,       // [KPTS,3]
    int N, int Ns)
{
    __shared__ float tile[32][33];
    __shared__ float s_kp[48];
    extern __shared__ unsigned char dyn[];

    if (blockIdx.x < BPREP_BLOCKS) {
        // ---- B prep: smem-tiled transpose + hi/lo split (proven) ----
        int b  = blockIdx.x;
        int k0 = (b % (KDIM / 32)) * 32;
        int n0 = (b / (KDIM / 32)) * 32;
        int tx = threadIdx.x & 31;
        int ty = threadIdx.x >> 5;      // 0..7

        #pragma unroll
        for (int j = 0; j < 4; ++j)
            tile[ty + 8 * j][tx] = W[(size_t)(k0 + ty + 8 * j) * COUT + n0 + tx];
        __syncthreads();

        #pragma unroll
        for (int j = 0; j < 4; ++j) {
            int n = n0 + ty + 8 * j;
            float v = tile[tx][ty + 8 * j];
            __nv_bfloat16 hi, lo;
            split_bf16(v, hi, lo);
            g_Bhi[(size_t)n * KDIM + k0 + tx] = hi;
            g_Blo[(size_t)n * KDIM + k0 + tx] = lo;
        }
        return;
    }

    int t    = threadIdx.x;
    int wid  = t >> 5;
    int lane = t & 31;

    if (t < KPTS * 3) s_kp[t] = kp[t];
    // Zero both stages entirely (pads stay zero; valid regions rewritten per query).
    for (int i = t; i < PREP_DYN / 4; i += 256) ((uint32_t*)dyn)[i] = 0;

    uint32_t ubase = smem_u32(dyn);
    int qbase = (blockIdx.x - BPREP_BLOCKS) * NQ;

    // ---- producer: influence weights + gather/convert into stage st ----
    auto produce = [&](int n, int st) {
        uint32_t uXh = ubase + st * STAGE_B + PX_H;
        uint32_t uXl = ubase + st * STAGE_B + PX_L;
        uint32_t uWh = ubase + st * STAGE_B + PW_H;
        uint32_t uWl = ubase + st * STAGE_B + PW_L;

        // gather + convert X rows: warp per h-row, 5 rows each (h = wid + 8i)
        #pragma unroll
        for (int i = 0; i < 5; ++i) {
            int h = wid + 8 * i;
            int idx = nb[(size_t)n * H + h];
            if ((unsigned)idx >= (unsigned)Ns) idx = 0;   // w=0 kills contribution
            float4 v = *(const float4*)(x + (size_t)idx * CIN + lane * 4);
            __nv_bfloat16 h0, h1, h2, h3, l0, l1, l2, l3;
            split_bf16(v.x, h0, l0);
            split_bf16(v.y, h1, l1);
            split_bf16(v.z, h2, l2);
            split_bf16(v.w, h3, l3);
            uint32_t off = (uint32_t)(h * 256 + ((lane * 8) ^ ((h & 7) * 16)));
            *(ushort4*)(uXh + off - ubase + dyn) = make_ushort4(bits(h0), bits(h1), bits(h2), bits(h3));
            *(ushort4*)(uXl + off - ubase + dyn) = make_ushort4(bits(l0), bits(l1), bits(l2), bits(l3));
        }

        // influence weights: threads 0..39, one h each
        if (t < H) {
            int h = t;
            float qx = q_pts[n * 3 + 0];
            float qy = q_pts[n * 3 + 1];
            float qz = q_pts[n * 3 + 2];
            int idx = nb[(size_t)n * H + h];
            bool valid = ((unsigned)idx < (unsigned)Ns);
            int safe = valid ? idx : 0;
            float px = s_pts[(size_t)safe * 3 + 0] - qx;
            float py = s_pts[(size_t)safe * 3 + 1] - qy;
            float pz = s_pts[(size_t)safe * 3 + 2] - qz;
            #pragma unroll
            for (int k = 0; k < KPTS; k++) {
                float dx = px - s_kp[k * 3 + 0];
                float dy = py - s_kp[k * 3 + 1];
                float dz = pz - s_kp[k * 3 + 2];
                float d2 = dx * dx + dy * dy + dz * dz;
                float w  = fmaxf(1.0f - sqrtf(d2) * KP_EXTENT_INV, 0.0f);
                w = valid ? w : 0.0f;
                __nv_bfloat16 wh, wl;
                split_bf16(w, wh, wl);
                uint32_t off = (uint32_t)(k * 128 + ((2 * h) ^ ((k & 7) * 16)));
                *(__nv_bfloat16*)(dyn + st * STAGE_B + PW_H + off) = wh;
                *(__nv_bfloat16*)(dyn + st * STAGE_B + PW_L + off) = wl;
            }
        }
    };

    // ---- consumer: mma + store (fragment paths identical to R14) ----
    auto consume = [&](int n, int st) {
        uint32_t uXhi = ubase + st * STAGE_B + PX_H;
        uint32_t uXlo = ubase + st * STAGE_B + PX_L;
        uint32_t uWhi = ubase + st * STAGE_B + PW_H;
        uint32_t uWlo = ubase + st * STAGE_B + PW_L;

        int c0w = wid * 16;
        float d0[4] = {0.f, 0.f, 0.f, 0.f};
        float d1[4] = {0.f, 0.f, 0.f, 0.f};

        #pragma unroll
        for (int ks = 0; ks < 3; ++ks) {
            int ar = lane & 15;
            uint32_t aoff = (uint32_t)(ar * 128 +
                            (((ks * 2 + (lane >> 4)) * 16) ^ ((ar & 7) * 16)));
            uint32_t ah0, ah1, ah2, ah3, al0, al1, al2, al3;
            ldm_x4(ah0, ah1, ah2, ah3, uWhi + aoff);
            ldm_x4(al0, al1, al2, al3, uWlo + aoff);

            int brow = ks * 16 + (lane & 7) + ((lane >> 3) & 1) * 8;
            uint32_t bcol = (uint32_t)(c0w * 2 + ((lane >> 4) * 16));
            uint32_t boff = (uint32_t)(brow * 256 + (bcol ^ ((brow & 7) * 16)));
            uint32_t bh0, bh1, bh2, bh3, bl0, bl1, bl2, bl3;
            ldm_x4_trans(bh0, bh1, bh2, bh3, uXhi + boff);
            ldm_x4_trans(bl0, bl1, bl2, bl3, uXlo + boff);

            mma_bf16(d0[0], d0[1], d0[2], d0[3], ah0, ah1, ah2, ah3, bh0, bh1);
            mma_bf16(d0[0], d0[1], d0[2], d0[3], ah0, ah1, ah2, ah3, bl0, bl1);
            mma_bf16(d0[0], d0[1], d0[2], d0[3], al0, al1, al2, al3, bh0, bh1);
            mma_bf16(d1[0], d1[1], d1[2], d1[3], ah0, ah1, ah2, ah3, bh2, bh3);
            mma_bf16(d1[0], d1[1], d1[2], d1[3], ah0, ah1, ah2, ah3, bl2, bl3);
            mma_bf16(d1[0], d1[1], d1[2], d1[3], al0, al1, al2, al3, bh2, bh3);
        }

        int k1 = lane >> 2;
        int k2 = k1 + 8;
        size_t base = (size_t)n * KDIM;
        #pragma unroll
        for (int nt = 0; nt < 2; ++nt) {
            float* dd = nt ? d1 : d0;
            int c = c0w + nt * 8 + 2 * (lane & 3);
            {
                __nv_bfloat16 a0, b0, a1, b1;
                split_bf16(dd[0], a0, b0);
                split_bf16(dd[1], a1, b1);
                *(ushort2*)(g_Ahi + base + (size_t)k1 * CIN + c) = make_ushort2(bits(a0), bits(a1));
                *(ushort2*)(g_Alo + base + (size_t)k1 * CIN + c) = make_ushort2(bits(b0), bits(b1));
            }
            if (k2 < KPTS) {
                __nv_bfloat16 a0, b0, a1, b1;
                split_bf16(dd[2], a0, b0);
                split_bf16(dd[3], a1, b1);
                *(ushort2*)(g_Ahi + base + (size_t)k2 * CIN + c) = make_ushort2(bits(a0), bits(a1));
                *(ushort2*)(g_Alo + base + (size_t)k2 * CIN + c) = make_ushort2(bits(b0), bits(b1));
            }
        }
    };

    // ---- pipelined loop: one __syncthreads per query ----
    __syncthreads();                       // zeroing complete
    if (qbase < N) produce(qbase, 0);      // prologue

    for (int q = 0; q < NQ; ++q) {
        __syncthreads();                   // stage q&1 ready; stage (q+1)&1 free
        if (q + 1 < NQ && qbase + q + 1 < N) produce(qbase + q + 1, (q + 1) & 1);
        if (qbase + q < N)                   consume(qbase + q, q & 1);
    }
}

// ---------------------------------------------------------------------------
// Kernel 2: mma.sync bf16 split GEMM, SPLIT-K = 3 (unchanged — proven).
// ---------------------------------------------------------------------------
#define KC        64
#define CHUNKS    (KDIM / KC)        // 30
#define CHUNKS_PK (CHUNKS / SPLITK)  // 10
#define SA_H  0
#define SA_L  8192
#define SB_H  16384
#define SB_L  32768
#define ST_BYTES 49152
#define SMEM_TOTAL (2 * ST_BYTES)    // 96 KB

__global__ void __launch_bounds__(256, 2) kp_mma_gemm_kernel(int N)
{
    extern __shared__ char smem[];
    uint32_t sbase = smem_u32(smem);
    int tid  = threadIdx.x;
    int wid  = tid >> 5;
    int lane = tid & 31;

    int mt    = blockIdx.x / SPLITK;
    int kz    = blockIdx.x % SPLITK;
    int m0    = mt * 64;
    int cbase = kz * CHUNKS_PK;

    float* Cp_out = g_Cpart[kz];

    int wm = wid & 1;
    int wn = wid >> 1;

    int seg = tid & 7;
    int rb  = tid >> 3;

    const __nv_bfloat16* Ah = g_Ahi;
    const __nv_bfloat16* Al = g_Alo;
    const __nv_bfloat16* Bh = g_Bhi;
    const __nv_bfloat16* Bl = g_Blo;

    float acc[2][4][4];
    #pragma unroll
    for (int i = 0; i < 2; i++)
        #pragma unroll
        for (int j = 0; j < 4; j++)
            #pragma unroll
            for (int q = 0; q < 4; q++) acc[i][j][q] = 0.0f;

    auto load_chunk = [&](int stage, int c) {
        uint32_t sb = sbase + stage * ST_BYTES;
        size_t c0 = (size_t)c * KC + (size_t)seg * 8;
        #pragma unroll
        for (int g = 0; g < 2; ++g) {
            int r  = g * 32 + rb;
            int ra = m0 + r; if (ra >= N) ra = N - 1;
            uint32_t off = swz(r, seg);
            cp_async16(sb + SA_H + off, Ah + (size_t)ra * KDIM + c0);
            cp_async16(sb + SA_L + off, Al + (size_t)ra * KDIM + c0);
        }
        #pragma unroll
        for (int g = 0; g < 4; ++g) {
            int r = g * 32 + rb;
            uint32_t off = swz(r, seg);
            cp_async16(sb + SB_H + off, Bh + (size_t)r * KDIM + c0);
            cp_async16(sb + SB_L + off, Bl + (size_t)r * KDIM + c0);
        }
        cp_async_commit();
    };

    int a_r15 = lane & 15;
    int a_kx  = lane >> 4;
    int b_r   = ((lane >> 4) << 3) + (lane & 7);
    int b_kx  = (lane >> 3) & 1;

    load_chunk(0, cbase);

    for (int ci = 0; ci < CHUNKS_PK; ++ci) {
        int cur = ci & 1;
        if (ci + 1 < CHUNKS_PK) load_chunk(cur ^ 1, cbase + ci + 1);

        if (ci + 1 < CHUNKS_PK) cp_async_wait<1>();
        else                    cp_async_wait<0>();
        __syncthreads();

        uint32_t sb = sbase + cur * ST_BYTES;

        #pragma unroll
        for (int ks = 0; ks < 4; ++ks) {
            uint32_t ah[2][4], al[2][4];
            #pragma unroll
            for (int mtt = 0; mtt < 2; ++mtt) {
                int r  = wm * 32 + mtt * 16 + a_r15;
                int sg = ks * 2 + a_kx;
                uint32_t off = swz(r, sg);
                ldm_x4(ah[mtt][0], ah[mtt][1], ah[mtt][2], ah[mtt][3], sb + SA_H + off);
                ldm_x4(al[mtt][0], al[mtt][1], al[mtt][2], al[mtt][3], sb + SA_L + off);
            }
            uint32_t bh[4][2], bl[4][2];
            #pragma unroll
            for (int nt2 = 0; nt2 < 2; ++nt2) {
                int r  = wn * 32 + nt2 * 16 + b_r;
                int sg = ks * 2 + b_kx;
                uint32_t off = swz(r, sg);
                uint32_t r0, r1, r2, r3;
                ldm_x4(r0, r1, r2, r3, sb + SB_H + off);
                bh[nt2 * 2 + 0][0] = r0; bh[nt2 * 2 + 0][1] = r1;
                bh[nt2 * 2 + 1][0] = r2; bh[nt2 * 2 + 1][1] = r3;
                ldm_x4(r0, r1, r2, r3, sb + SB_L + off);
                bl[nt2 * 2 + 0][0] = r0; bl[nt2 * 2 + 0][1] = r1;
                bl[nt2 * 2 + 1][0] = r2; bl[nt2 * 2 + 1][1] = r3;
            }
            #pragma unroll
            for (int mtt = 0; mtt < 2; ++mtt)
                #pragma unroll
                for (int nt = 0; nt < 4; ++nt) {
                    float* cc = acc[mtt][nt];
                    mma_bf16(cc[0], cc[1], cc[2], cc[3],
                             ah[mtt][0], ah[mtt][1], ah[mtt][2], ah[mtt][3],
                             bh[nt][0], bh[nt][1]);
                    mma_bf16(cc[0], cc[1], cc[2], cc[3],
                             ah[mtt][0], ah[mtt][1], ah[mtt][2], ah[mtt][3],
                             bl[nt][0], bl[nt][1]);
                    mma_bf16(cc[0], cc[1], cc[2], cc[3],
                             al[mtt][0], al[mtt][1], al[mtt][2], al[mtt][3],
                             bh[nt][0], bh[nt][1]);
                }
        }
        __syncthreads();
    }

    int tq = lane >> 2;
    int tr = (lane & 3) * 2;
    #pragma unroll
    for (int mtt = 0; mtt < 2; ++mtt) {
        #pragma unroll
        for (int nt = 0; nt < 4; ++nt) {
            int gm = m0 + wm * 32 + mtt * 16 + tq;
            int gn = wn * 32 + nt * 8 + tr;
            float* cc = acc[mtt][nt];
            if (gm < N)     *(float2*)&Cp_out[(size_t)gm * COUT + gn]       = make_float2(cc[0], cc[1]);
            if (gm + 8 < N) *(float2*)&Cp_out[(size_t)(gm + 8) * COUT + gn] = make_float2(cc[2], cc[3]);
        }
    }
}

// ---------------------------------------------------------------------------
// Kernel 3: combine split-K partials.  out = p0 + p1 + p2  (float4 vectorized)
// ---------------------------------------------------------------------------
__global__ void __launch_bounds__(256) kp_splitk_add_kernel(float* __restrict__ out, int total4)
{
    int i = blockIdx.x * blockDim.x + threadIdx.x;
    if (i < total4) {
        const float4* p0 = (const float4*)g_Cpart[0];
        const float4* p1 = (const float4*)g_Cpart[1];
        const float4* p2 = (const float4*)g_Cpart[2];
        float4 a = p0[i];
        float4 b = p1[i];
        float4 c = p2[i];
        ((float4*)out)[i] = make_float4(a.x + b.x + c.x, a.y + b.y + c.y,
                                        a.z + b.z + c.z, a.w + b.w + c.w);
    }
}

// ---------------------------------------------------------------------------
// kernel_launch
// Inputs: q_pts [N,3] f32, s_pts [Ns,3] f32, neighb_inds [N,H] i32,
// x [Ns,CIN] f32, kernel_points [KPTS,3] f32, weights [KPTS,CIN,COUT] f32.
// Output: [N,COUT] f32.
// ---------------------------------------------------------------------------
extern "C" void kernel_launch(void* const* d_in, const int* in_sizes, int n_in,
                              void* d_out, int out_size)
{
    const float* q_pts = (const float*)d_in[0];
    const float* s_pts = (const float*)d_in[1];
    const int*   nb    = (const int*)d_in[2];
    const float* x     = (const float*)d_in[3];
    const float* kp    = (const float*)d_in[4];
    const float* w     = (const float*)d_in[5];
    float*       out   = (float*)d_out;

    int N  = in_sizes[0] / 3;
    int Ns = in_sizes[1] / 3;

    static int smem_set = 0;
    if (!smem_set) {
        cudaFuncSetAttribute(kp_mma_gemm_kernel,
                             cudaFuncAttributeMaxDynamicSharedMemorySize, SMEM_TOTAL);
        cudaFuncSetAttribute(kp_prep_weight_kernel,
                             cudaFuncAttributeMaxDynamicSharedMemorySize, PREP_DYN);
        smem_set = 1;
    }

    int grid1 = BPREP_BLOCKS + (N + NQ - 1) / NQ;
    kp_prep_weight_kernel<<<grid1, 256, PREP_DYN>>>(w, q_pts, s_pts, nb, x, kp, N, Ns);

    int mtiles = (N + 63) / 64;
    kp_mma_gemm_kernel<<<mtiles * SPLITK, 256, SMEM_TOTAL>>>(N);

    int total4 = (N * COUT) / 4;
    kp_splitk_add_kernel<<<(total4 + 255) / 256, 256>>>(out, total4);
}

// round 17
// speedup vs baseline: 1.5632x; 1.4013x over previous
#include <cuda_runtime.h>
#include <cuda_bf16.h>
#include <cstdint>

// Problem constants (fixed shapes from the reference)
#define H     40
#define KPTS  15
#define CIN   128
#define COUT  128
#define NMAX  20000
#define KDIM  (KPTS * CIN)   // 1920
#define KP_EXTENT_INV (1.0f / 1.2f)

// ---------------------------------------------------------------------------
// Static scratch: split-bf16 operands + split-K partial outputs.
// ---------------------------------------------------------------------------
__device__ __nv_bfloat16 g_Ahi[(size_t)NMAX * KDIM];
__device__ __nv_bfloat16 g_Alo[(size_t)NMAX * KDIM];
__device__ __nv_bfloat16 g_Bhi[(size_t)COUT * KDIM];
__device__ __nv_bfloat16 g_Blo[(size_t)COUT * KDIM];
#define SPLITK 3
__device__ float         g_Cpart[SPLITK][(size_t)NMAX * COUT];   // split-K partials

// ---------------------------------------------------------------------------
// PTX helpers (baseline sm_80+ instructions — safe for compute_103)
// ---------------------------------------------------------------------------
__device__ __forceinline__ uint32_t smem_u32(const void* p) {
    uint32_t a;
    asm("{ .reg .u64 t; cvta.to.shared.u64 t, %1; cvt.u32.u64 %0, t; }" : "=r"(a) : "l"(p));
    return a;
}
__device__ __forceinline__ void cp_async16(uint32_t dst, const void* src) {
    asm volatile("cp.async.cg.shared.global [%0], [%1], 16;\n" :: "r"(dst), "l"(src) : "memory");
}
__device__ __forceinline__ void cp_async_commit() {
    asm volatile("cp.async.commit_group;" ::: "memory");
}
template <int NN>
__device__ __forceinline__ void cp_async_wait() {
    asm volatile("cp.async.wait_group %0;" :: "n"(NN) : "memory");
}
__device__ __forceinline__ void ldm_x4(uint32_t& r0, uint32_t& r1, uint32_t& r2, uint32_t& r3,
                                       uint32_t addr) {
    asm volatile("ldmatrix.sync.aligned.m8n8.x4.shared.b16 {%0,%1,%2,%3}, [%4];"
                 : "=r"(r0), "=r"(r1), "=r"(r2), "=r"(r3) : "r"(addr));
}
__device__ __forceinline__ void mma_bf16(float& c0, float& c1, float& c2, float& c3,
                                         uint32_t a0, uint32_t a1, uint32_t a2, uint32_t a3,
                                         uint32_t b0, uint32_t b1) {
    asm volatile("mma.sync.aligned.m16n8k16.row.col.f32.bf16.bf16.f32 "
                 "{%0,%1,%2,%3}, {%4,%5,%6,%7}, {%8,%9}, {%0,%1,%2,%3};"
                 : "+f"(c0), "+f"(c1), "+f"(c2), "+f"(c3)
                 : "r"(a0), "r"(a1), "r"(a2), "r"(a3), "r"(b0), "r"(b1));
}

__device__ __forceinline__ void split_bf16(float v, __nv_bfloat16& hi, __nv_bfloat16& lo) {
    hi = __float2bfloat16_rn(v);
    lo = __float2bfloat16_rn(v - __bfloat162float(hi));
}
__device__ __forceinline__ unsigned short bits(__nv_bfloat16 v) {
    return __bfloat16_as_ushort(v);
}

// SW128 swizzled byte offset for (row r [128B rows], 16B segment seg)
__device__ __forceinline__ uint32_t swz(int r, int seg) {
    return (uint32_t)(r * 128 + ((seg * 16) ^ ((r & 7) * 16)));
}

// ---------------------------------------------------------------------------
// Kernel 1 (combined): blocks [0, BPREP_BLOCKS) transpose+split the weights;
// remaining blocks: R10-proven scalar warp-per-query aggregation, with the
// neighbor-feature gather staged through smem via per-lane cp.async
// (double-buffered 8-row stages; no barriers — each lane consumes only the
// 16 bytes it copied itself).
// ---------------------------------------------------------------------------
#define BPREP_BLOCKS ((KDIM / 32) * (COUT / 32))   // 60 * 4 = 240
// dynamic smem: fb[8 warps][2 stages][8 rows][512 B] = 64 KB
#define FB_WARP   8192
#define FB_STAGE  4096
#define FB_ROW    512
#define PREP_DYN  (8 * FB_WARP)

__global__ void __launch_bounds__(256) kp_prep_weight_kernel(
    const float* __restrict__ W,        // [KDIM, COUT]
    const float* __restrict__ q_pts,    // [N,3]
    const float* __restrict__ s_pts,    // [Ns,3]
    const int*   __restrict__ nb,       // [N,H]
    const float* __restrict__ x,        // [Ns,CIN]
    const float* __restrict__ kp,       // [KPTS,3]
    int N, int Ns)
{
    __shared__ float tile[32][33];
    __shared__ float s_kp[48];
    __shared__ float s_w[8][H][16];
    __shared__ int   s_idx[8][H];
    extern __shared__ unsigned char fb[];

    if (blockIdx.x < BPREP_BLOCKS) {
        // ---- B prep: smem-tiled transpose + hi/lo split (proven) ----
        int b  = blockIdx.x;
        int k0 = (b % (KDIM / 32)) * 32;
        int n0 = (b / (KDIM / 32)) * 32;
        int tx = threadIdx.x & 31;
        int ty = threadIdx.x >> 5;      // 0..7

        #pragma unroll
        for (int j = 0; j < 4; ++j)
            tile[ty + 8 * j][tx] = W[(size_t)(k0 + ty + 8 * j) * COUT + n0 + tx];
        __syncthreads();

        #pragma unroll
        for (int j = 0; j < 4; ++j) {
            int n = n0 + ty + 8 * j;
            float v = tile[tx][ty + 8 * j];
            __nv_bfloat16 hi, lo;
            split_bf16(v, hi, lo);
            g_Bhi[(size_t)n * KDIM + k0 + tx] = hi;
            g_Blo[(size_t)n * KDIM + k0 + tx] = lo;
        }
        return;
    }

    // ---- Influence weighting + aggregation (R10-proven, cp.async gather) ----
    int wid  = threadIdx.x >> 5;
    int lane = threadIdx.x & 31;
    int n    = (blockIdx.x - BPREP_BLOCKS) * 8 + wid;

    if (threadIdx.x < KPTS * 3) s_kp[threadIdx.x] = kp[threadIdx.x];
    __syncthreads();

    if (n < N) {
        float qx = q_pts[n * 3 + 0];
        float qy = q_pts[n * 3 + 1];
        float qz = q_pts[n * 3 + 2];

        for (int h = lane; h < H; h += 32) {
            int idx = nb[(size_t)n * H + h];
            bool valid = ((unsigned)idx < (unsigned)Ns);
            int safe = valid ? idx : 0;
            s_idx[wid][h] = safe;
            float px = s_pts[(size_t)safe * 3 + 0] - qx;
            float py = s_pts[(size_t)safe * 3 + 1] - qy;
            float pz = s_pts[(size_t)safe * 3 + 2] - qz;
            #pragma unroll
            for (int k = 0; k < KPTS; k++) {
                float dx = px - s_kp[k * 3 + 0];
                float dy = py - s_kp[k * 3 + 1];
                float dz = pz - s_kp[k * 3 + 2];
                float d2 = dx * dx + dy * dy + dz * dz;
                float w  = fmaxf(1.0f - sqrtf(d2) * KP_EXTENT_INV, 0.0f);
                s_w[wid][h][k] = valid ? w : 0.0f;
            }
            s_w[wid][h][15] = 0.0f;
        }
        __syncwarp();

        float4 acc[KPTS];
        #pragma unroll
        for (int k = 0; k < KPTS; k++) acc[k] = make_float4(0.f, 0.f, 0.f, 0.f);

        const float* xl = x + (lane << 2);
        unsigned char* fwb = fb + wid * FB_WARP + lane * 16;
        uint32_t ufwb = smem_u32(fwb);

        // Prologue: stage 0 (h = 0..7) into buffer 0.
        #pragma unroll
        for (int r = 0; r < 8; ++r) {
            int idx = s_idx[wid][r];
            cp_async16(ufwb + 0 * FB_STAGE + r * FB_ROW, xl + (size_t)idx * CIN);
        }
        cp_async_commit();

        #pragma unroll
        for (int s = 0; s < 5; ++s) {
            if (s < 4) {
                #pragma unroll
                for (int r = 0; r < 8; ++r) {
                    int idx = s_idx[wid][(s + 1) * 8 + r];
                    cp_async16(ufwb + ((s + 1) & 1) * FB_STAGE + r * FB_ROW,
                               xl + (size_t)idx * CIN);
                }
                cp_async_commit();
                cp_async_wait<1>();      // stage s complete; s+1 in flight
            } else {
                cp_async_wait<0>();
            }

            unsigned char* stg = fwb + (s & 1) * FB_STAGE;
            #pragma unroll
            for (int r = 0; r < 8; ++r) {
                int h = s * 8 + r;
                float4 f = *(const float4*)(stg + r * FB_ROW);
                float wk[16];
                const float4* wv = (const float4*)s_w[wid][h];
                *(float4*)&wk[0]  = wv[0];
                *(float4*)&wk[4]  = wv[1];
                *(float4*)&wk[8]  = wv[2];
                *(float4*)&wk[12] = wv[3];
                #pragma unroll
                for (int k = 0; k < KPTS; k++) {
                    acc[k].x = fmaf(wk[k], f.x, acc[k].x);
                    acc[k].y = fmaf(wk[k], f.y, acc[k].y);
                    acc[k].z = fmaf(wk[k], f.z, acc[k].z);
                    acc[k].w = fmaf(wk[k], f.w, acc[k].w);
                }
            }
        }

        size_t rowoff = (size_t)n * KDIM + (lane << 2);
        #pragma unroll
        for (int k = 0; k < KPTS; k++) {
            __nv_bfloat16 h0, h1, h2, h3, l0, l1, l2, l3;
            split_bf16(acc[k].x, h0, l0);
            split_bf16(acc[k].y, h1, l1);
            split_bf16(acc[k].z, h2, l2);
            split_bf16(acc[k].w, h3, l3);
            ushort4 vh = make_ushort4(bits(h0), bits(h1), bits(h2), bits(h3));
            ushort4 vl = make_ushort4(bits(l0), bits(l1), bits(l2), bits(l3));
            *(ushort4*)(g_Ahi + rowoff + (size_t)k * CIN) = vh;
            *(ushort4*)(g_Alo + rowoff + (size_t)k * CIN) = vl;
        }
    }
}

// ---------------------------------------------------------------------------
// Kernel 2: mma.sync bf16 split GEMM, SPLIT-K = 3 (unchanged — proven).
// ---------------------------------------------------------------------------
#define KC        64
#define CHUNKS    (KDIM / KC)        // 30
#define CHUNKS_PK (CHUNKS / SPLITK)  // 10
#define SA_H  0
#define SA_L  8192
#define SB_H  16384
#define SB_L  32768
#define ST_BYTES 49152
#define SMEM_TOTAL (2 * ST_BYTES)    // 96 KB

__global__ void __launch_bounds__(256, 2) kp_mma_gemm_kernel(int N)
{
    extern __shared__ char smem[];
    uint32_t sbase = smem_u32(smem);
    int tid  = threadIdx.x;
    int wid  = tid >> 5;
    int lane = tid & 31;

    int mt    = blockIdx.x / SPLITK;
    int kz    = blockIdx.x % SPLITK;
    int m0    = mt * 64;
    int cbase = kz * CHUNKS_PK;

    float* Cp_out = g_Cpart[kz];

    int wm = wid & 1;
    int wn = wid >> 1;

    int seg = tid & 7;
    int rb  = tid >> 3;

    const __nv_bfloat16* Ah = g_Ahi;
    const __nv_bfloat16* Al = g_Alo;
    const __nv_bfloat16* Bh = g_Bhi;
    const __nv_bfloat16* Bl = g_Blo;

    float acc[2][4][4];
    #pragma unroll
    for (int i = 0; i < 2; i++)
        #pragma unroll
        for (int j = 0; j < 4; j++)
            #pragma unroll
            for (int q = 0; q < 4; q++) acc[i][j][q] = 0.0f;

    auto load_chunk = [&](int stage, int c) {
        uint32_t sb = sbase + stage * ST_BYTES;
        size_t c0 = (size_t)c * KC + (size_t)seg * 8;
        #pragma unroll
        for (int g = 0; g < 2; ++g) {
            int r  = g * 32 + rb;
            int ra = m0 + r; if (ra >= N) ra = N - 1;
            uint32_t off = swz(r, seg);
            cp_async16(sb + SA_H + off, Ah + (size_t)ra * KDIM + c0);
            cp_async16(sb + SA_L + off, Al + (size_t)ra * KDIM + c0);
        }
        #pragma unroll
        for (int g = 0; g < 4; ++g) {
            int r = g * 32 + rb;
            uint32_t off = swz(r, seg);
            cp_async16(sb + SB_H + off, Bh + (size_t)r * KDIM + c0);
            cp_async16(sb + SB_L + off, Bl + (size_t)r * KDIM + c0);
        }
        cp_async_commit();
    };

    int a_r15 = lane & 15;
    int a_kx  = lane >> 4;
    int b_r   = ((lane >> 4) << 3) + (lane & 7);
    int b_kx  = (lane >> 3) & 1;

    load_chunk(0, cbase);

    for (int ci = 0; ci < CHUNKS_PK; ++ci) {
        int cur = ci & 1;
        if (ci + 1 < CHUNKS_PK) load_chunk(cur ^ 1, cbase + ci + 1);

        if (ci + 1 < CHUNKS_PK) cp_async_wait<1>();
        else                    cp_async_wait<0>();
        __syncthreads();

        uint32_t sb = sbase + cur * ST_BYTES;

        #pragma unroll
        for (int ks = 0; ks < 4; ++ks) {
            uint32_t ah[2][4], al[2][4];
            #pragma unroll
            for (int mtt = 0; mtt < 2; ++mtt) {
                int r  = wm * 32 + mtt * 16 + a_r15;
                int sg = ks * 2 + a_kx;
                uint32_t off = swz(r, sg);
                ldm_x4(ah[mtt][0], ah[mtt][1], ah[mtt][2], ah[mtt][3], sb + SA_H + off);
                ldm_x4(al[mtt][0], al[mtt][1], al[mtt][2], al[mtt][3], sb + SA_L + off);
            }
            uint32_t bh[4][2], bl[4][2];
            #pragma unroll
            for (int nt2 = 0; nt2 < 2; ++nt2) {
                int r  = wn * 32 + nt2 * 16 + b_r;
                int sg = ks * 2 + b_kx;
                uint32_t off = swz(r, sg);
                uint32_t r0, r1, r2, r3;
                ldm_x4(r0, r1, r2, r3, sb + SB_H + off);
                bh[nt2 * 2 + 0][0] = r0; bh[nt2 * 2 + 0][1] = r1;
                bh[nt2 * 2 + 1][0] = r2; bh[nt2 * 2 + 1][1] = r3;
                ldm_x4(r0, r1, r2, r3, sb + SB_L + off);
                bl[nt2 * 2 + 0][0] = r0; bl[nt2 * 2 + 0][1] = r1;
                bl[nt2 * 2 + 1][0] = r2; bl[nt2 * 2 + 1][1] = r3;
            }
            #pragma unroll
            for (int mtt = 0; mtt < 2; ++mtt)
                #pragma unroll
                for (int nt = 0; nt < 4; ++nt) {
                    float* cc = acc[mtt][nt];
                    mma_bf16(cc[0], cc[1], cc[2], cc[3],
                             ah[mtt][0], ah[mtt][1], ah[mtt][2], ah[mtt][3],
                             bh[nt][0], bh[nt][1]);
                    mma_bf16(cc[0], cc[1], cc[2], cc[3],
                             ah[mtt][0], ah[mtt][1], ah[mtt][2], ah[mtt][3],
                             bl[nt][0], bl[nt][1]);
                    mma_bf16(cc[0], cc[1], cc[2], cc[3],
                             al[mtt][0], al[mtt][1], al[mtt][2], al[mtt][3],
                             bh[nt][0], bh[nt][1]);
                }
        }
        __syncthreads();
    }

    int tq = lane >> 2;
    int tr = (lane & 3) * 2;
    #pragma unroll
    for (int mtt = 0; mtt < 2; ++mtt) {
        #pragma unroll
        for (int nt = 0; nt < 4; ++nt) {
            int gm = m0 + wm * 32 + mtt * 16 + tq;
            int gn = wn * 32 + nt * 8 + tr;
            float* cc = acc[mtt][nt];
            if (gm < N)     *(float2*)&Cp_out[(size_t)gm * COUT + gn]       = make_float2(cc[0], cc[1]);
            if (gm + 8 < N) *(float2*)&Cp_out[(size_t)(gm + 8) * COUT + gn] = make_float2(cc[2], cc[3]);
        }
    }
}

// ---------------------------------------------------------------------------
// Kernel 3: combine split-K partials.  out = p0 + p1 + p2  (float4 vectorized)
// ---------------------------------------------------------------------------
__global__ void __launch_bounds__(256) kp_splitk_add_kernel(float* __restrict__ out, int total4)
{
    int i = blockIdx.x * blockDim.x + threadIdx.x;
    if (i < total4) {
        const float4* p0 = (const float4*)g_Cpart[0];
        const float4* p1 = (const float4*)g_Cpart[1];
        const float4* p2 = (const float4*)g_Cpart[2];
        float4 a = p0[i];
        float4 b = p1[i];
        float4 c = p2[i];
        ((float4*)out)[i] = make_float4(a.x + b.x + c.x, a.y + b.y + c.y,
                                        a.z + b.z + c.z, a.w + b.w + c.w);
    }
}

// ---------------------------------------------------------------------------
// kernel_launch
// Inputs: q_pts [N,3] f32, s_pts [Ns,3] f32, neighb_inds [N,H] i32,
// x [Ns,CIN] f32, kernel_points [KPTS,3] f32, weights [KPTS,CIN,COUT] f32.
// Output: [N,COUT] f32.
// ---------------------------------------------------------------------------
extern "C" void kernel_launch(void* const* d_in, const int* in_sizes, int n_in,
                              void* d_out, int out_size)
{
    const float* q_pts = (const float*)d_in[0];
    const float* s_pts = (const float*)d_in[1];
    const int*   nb    = (const int*)d_in[2];
    const float* x     = (const float*)d_in[3];
    const float* kp    = (const float*)d_in[4];
    const float* w     = (const float*)d_in[5];
    float*       out   = (float*)d_out;

    int N  = in_sizes[0] / 3;
    int Ns = in_sizes[1] / 3;

    static int smem_set = 0;
    if (!smem_set) {
        cudaFuncSetAttribute(kp_mma_gemm_kernel,
                             cudaFuncAttributeMaxDynamicSharedMemorySize, SMEM_TOTAL);
        cudaFuncSetAttribute(kp_prep_weight_kernel,
                             cudaFuncAttributeMaxDynamicSharedMemorySize, PREP_DYN);
        smem_set = 1;
    }

    int grid1 = BPREP_BLOCKS + (N + 7) / 8;
    kp_prep_weight_kernel<<<grid1, 256, PREP_DYN>>>(w, q_pts, s_pts, nb, x, kp, N, Ns);

    int mtiles = (N + 63) / 64;
    kp_mma_gemm_kernel<<<mtiles * SPLITK, 256, SMEM_TOTAL>>>(N);

    int total4 = (N * COUT) / 4;
    kp_splitk_add_kernel<<<(total4 + 255) / 256, 256>>>(out, total4);
}